// round 3
// baseline (speedup 1.0000x reference)
#include <cuda_runtime.h>
#include <math.h>

#define NN    50000
#define EE    600000
#define DD    128
#define RREL2 474          /* 2R */
#define QQ    128
#define KTOT  1664         /* 13*D */
#define RELSZ (RREL2*DD)   /* 60672 */

// -------- scratch (static device globals; no allocation allowed) --------
__device__ float    g_rel[RELSZ];
__device__ int      g_row_start[NN + 1];
__device__ int      g_cursor[NN];
__device__ unsigned g_packed[EE];                 // src (16b) | attr<<16 (9b)
__device__ float    g_feat4[(size_t)NN * 4 * DD]; // [N, 512] interleaved mean,max,min,std
__device__ float    g_logdeg[NN];
__device__ float    g_logdeg_mean;

__device__ __forceinline__ unsigned f2tf32(float f) {
    unsigned r;
    asm("cvt.rna.tf32.f32 %0, %1;" : "=r"(r) : "f"(f));
    return r;
}

// ======================= K1: rel = query @ Wr^T + br =======================
__global__ void rel_kernel(const float* __restrict__ Wr,
                           const float* __restrict__ br,
                           const float* __restrict__ query) {
    int warp = (blockIdx.x * blockDim.x + threadIdx.x) >> 5;
    int lane = threadIdx.x & 31;
    if (warp >= RELSZ) return;
    const float* w = Wr + (size_t)warp * QQ;
    float s = w[lane]      * __ldg(&query[lane])
            + w[lane + 32] * __ldg(&query[lane + 32])
            + w[lane + 64] * __ldg(&query[lane + 64])
            + w[lane + 96] * __ldg(&query[lane + 96]);
    #pragma unroll
    for (int o = 16; o; o >>= 1) s += __shfl_xor_sync(0xffffffffu, s, o);
    if (lane == 0) g_rel[warp] = s + br[warp];
}

// ============ K2: exclusive scan of (int)degree -> row_start, cursor =========
__global__ void scan_kernel(const float* __restrict__ degout) {
    __shared__ int wsum[32];
    __shared__ int carry;
    int t = threadIdx.x, lane = t & 31, w = t >> 5;
    if (t == 0) carry = 0;
    __syncthreads();
    for (int base = 0; base < NN; base += 1024) {
        int i = base + t;
        int v = (i < NN) ? (int)(degout[i] + 0.5f) : 0;
        int x = v;
        #pragma unroll
        for (int o = 1; o < 32; o <<= 1) {
            int y = __shfl_up_sync(0xffffffffu, x, o);
            if (lane >= o) x += y;
        }
        if (lane == 31) wsum[w] = x;
        __syncthreads();
        if (w == 0) {
            int s = wsum[lane];
            #pragma unroll
            for (int o = 1; o < 32; o <<= 1) {
                int y = __shfl_up_sync(0xffffffffu, s, o);
                if (lane >= o) s += y;
            }
            wsum[lane] = s;
        }
        __syncthreads();
        int excl = x - v + (w ? wsum[w - 1] : 0) + carry;
        if (i < NN) { g_row_start[i] = excl; g_cursor[i] = excl; }
        __syncthreads();
        if (t == 1023) carry = excl + v;
        __syncthreads();
    }
    if (t == 0) g_row_start[NN] = carry;
}

// ================= K3: bucket edges into CSR slots ========================
__global__ void fill_kernel(const int* __restrict__ ei,
                            const int* __restrict__ ea) {
    int e = blockIdx.x * blockDim.x + threadIdx.x;
    if (e >= EE) return;
    int src = ei[e];
    int dst = ei[EE + e];
    int a   = ea[e];
    int pos = atomicAdd(&g_cursor[dst], 1);
    g_packed[pos] = (unsigned)src | ((unsigned)a << 16);
}

// ====== K4: per-node gather reduction (no atomics), fused stats epilogue ======
__global__ void agg_kernel(const float* __restrict__ nf,
                           const float* __restrict__ boundary,
                           const float* __restrict__ degout) {
    int n    = (blockIdx.x * blockDim.x + threadIdx.x) >> 5;
    int lane = threadIdx.x & 31;
    if (n >= NN) return;
    int beg = g_row_start[n], end = g_row_start[n + 1];

    float sum[4], sq[4], mx[4], mn[4];
    #pragma unroll
    for (int i = 0; i < 4; i++) { sum[i] = 0.f; sq[i] = 0.f; mx[i] = -INFINITY; mn[i] = INFINITY; }

    for (int e = beg; e < end; e++) {
        unsigned p = g_packed[e];
        const float* sp = nf    + (size_t)(p & 0xFFFFu) * DD;
        const float* fp = g_rel + (size_t)(p >> 16) * DD;
        #pragma unroll
        for (int i = 0; i < 4; i++) {
            int c = lane + 32 * i;
            float m = sp[c] * fp[c];
            sum[i] += m;
            sq[i]  += m * m;
            mx[i]   = fmaxf(mx[i], m);
            mn[i]   = fminf(mn[i], m);
        }
    }

    float d0  = degout[n];
    float deg = d0 + 1.0f;
    bool  has_edge = (d0 > 0.0f);
    float inv = 1.0f / deg;

    #pragma unroll
    for (int i = 0; i < 4; i++) {
        int c = lane + 32 * i;
        float b = boundary[(size_t)n * DD + c];
        float mean   = (sum[i] + b) * inv;
        float sqmean = (sq[i] + b * b) * inv;
        float vmx = has_edge ? mx[i] : 0.0f;
        float vmn = has_edge ? mn[i] : 0.0f;
        vmx = fmaxf(vmx, b);
        vmn = fminf(vmn, b);
        float sd = sqrtf(fmaxf(sqmean - mean * mean, 1e-6f));
        float4 v = make_float4(mean, vmx, vmn, sd);
        *(float4*)&g_feat4[(size_t)n * 512 + 4 * c] = v;
    }
    if (lane == 0) g_logdeg[n] = logf(deg);
}

// ================= K5: deterministic mean of log(deg) ======================
__global__ void mean_kernel() {
    __shared__ float sh[1024];
    float s = 0.f;
    for (int i = threadIdx.x; i < NN; i += 1024) s += g_logdeg[i];
    sh[threadIdx.x] = s;
    __syncthreads();
    for (int o = 512; o; o >>= 1) {
        if (threadIdx.x < (unsigned)o) sh[threadIdx.x] += sh[threadIdx.x + o];
        __syncthreads();
    }
    if (threadIdx.x == 0) g_logdeg_mean = sh[0] / (float)NN;
}

// ===== K6: tf32 tensor-core GEMM: out = relu([nf | feat4 (x) scales] @ Wlin^T + blin)
// Tile: 128x128 per block, BK=32. 8 warps in 4(m) x 2(n) grid; each warp
// 32 rows x 64 cols via m16n8k8 tf32 mma. Smem stride 36 -> conflict-free
// fragment loads (bank = (4g+t) mod 32, all 32 lanes distinct).
#define BK 32
#define XS_STRIDE 36

__global__ void __launch_bounds__(256, 2)
gemm_kernel(const float* __restrict__ nf,
            const float* __restrict__ Wlin,
            const float* __restrict__ blin,
            float* __restrict__ out) {
    __shared__ unsigned Xs[128 * XS_STRIDE];
    __shared__ unsigned Ws[128 * XS_STRIDE];
    __shared__ float sc1[128];
    __shared__ float sc2[128];

    const int t    = threadIdx.x;
    const int n0   = blockIdx.x * 128;
    const int warp = t >> 5;
    const int lane = t & 31;
    const int g    = lane >> 2;      // group id (0..7)
    const int tg   = lane & 3;       // thread in group (0..3)
    const int wr   = warp >> 1;      // warp row 0..3 (owns 32 m-rows)
    const int wc   = warp & 1;       // warp col 0..1 (owns 64 n-cols)

    if (t < 128) {
        int n = n0 + t;
        float scale = 0.f;
        if (n < NN) scale = g_logdeg[n] / (g_logdeg_mean + 1e-10f);
        sc1[t] = scale;
        sc2[t] = 1.0f / fmaxf(scale, 0.01f);
    }
    __syncthreads();

    float acc[2][8][4];
    #pragma unroll
    for (int s = 0; s < 2; s++)
        #pragma unroll
        for (int nt = 0; nt < 8; nt++)
            #pragma unroll
            for (int r = 0; r < 4; r++) acc[s][nt][r] = 0.f;

    for (int k0 = 0; k0 < KTOT; k0 += BK) {
        // ---- build X tile (virtual) and load W tile, tf32-converted ----
        #pragma unroll
        for (int i = 0; i < 16; i++) {
            int idx = t + i * 256;           // 0..4095
            int row = idx >> 5;              // 0..127
            int col = idx & 31;
            int c   = k0 + col;
            // X
            int n = n0 + row;
            float v = 0.f;
            if (n < NN) {
                if (c < DD) {
                    v = nf[(size_t)n * DD + c];
                } else {
                    int m = c - DD;
                    int q = m / 3;
                    int s3 = m - 3 * q;
                    float f = g_feat4[(size_t)n * 512 + q];
                    v = (s3 == 0) ? f : (s3 == 1 ? f * sc1[row] : f * sc2[row]);
                }
            }
            Xs[row * XS_STRIDE + col] = f2tf32(v);
            // W
            Ws[row * XS_STRIDE + col] = f2tf32(Wlin[(size_t)row * KTOT + c]);
        }
        __syncthreads();

        #pragma unroll
        for (int kk = 0; kk < BK; kk += 8) {
            unsigned a[2][4], b[8][2];
            #pragma unroll
            for (int s = 0; s < 2; s++) {
                int rbase = (wr * 32 + s * 16) * XS_STRIDE + kk;
                a[s][0] = Xs[rbase + g * XS_STRIDE + tg];
                a[s][1] = Xs[rbase + (g + 8) * XS_STRIDE + tg];
                a[s][2] = Xs[rbase + g * XS_STRIDE + tg + 4];
                a[s][3] = Xs[rbase + (g + 8) * XS_STRIDE + tg + 4];
            }
            #pragma unroll
            for (int nt = 0; nt < 8; nt++) {
                int jbase = (wc * 64 + nt * 8 + g) * XS_STRIDE + kk;
                b[nt][0] = Ws[jbase + tg];
                b[nt][1] = Ws[jbase + tg + 4];
            }
            #pragma unroll
            for (int s = 0; s < 2; s++)
                #pragma unroll
                for (int nt = 0; nt < 8; nt++) {
                    asm volatile(
                        "mma.sync.aligned.m16n8k8.row.col.f32.tf32.tf32.f32 "
                        "{%0,%1,%2,%3},{%4,%5,%6,%7},{%8,%9},{%0,%1,%2,%3};"
                        : "+f"(acc[s][nt][0]), "+f"(acc[s][nt][1]),
                          "+f"(acc[s][nt][2]), "+f"(acc[s][nt][3])
                        : "r"(a[s][0]), "r"(a[s][1]), "r"(a[s][2]), "r"(a[s][3]),
                          "r"(b[nt][0]), "r"(b[nt][1]));
                }
        }
        __syncthreads();
    }

    // ---- epilogue: bias + relu ----
    #pragma unroll
    for (int s = 0; s < 2; s++) {
        int r0 = n0 + wr * 32 + s * 16 + g;
        #pragma unroll
        for (int nt = 0; nt < 8; nt++) {
            int j = wc * 64 + nt * 8 + 2 * tg;
            float b0 = __ldg(&blin[j]);
            float b1 = __ldg(&blin[j + 1]);
            if (r0 < NN) {
                float2 v;
                v.x = fmaxf(acc[s][nt][0] + b0, 0.f);
                v.y = fmaxf(acc[s][nt][1] + b1, 0.f);
                *(float2*)&out[(size_t)r0 * DD + j] = v;
            }
            if (r0 + 8 < NN) {
                float2 v;
                v.x = fmaxf(acc[s][nt][2] + b0, 0.f);
                v.y = fmaxf(acc[s][nt][3] + b1, 0.f);
                *(float2*)&out[(size_t)(r0 + 8) * DD + j] = v;
            }
        }
    }
}

// ============================== launch ====================================
extern "C" void kernel_launch(void* const* d_in, const int* in_sizes, int n_in,
                              void* d_out, int out_size) {
    const float* nf    = (const float*)d_in[0];   // node_features [N,D]
    const float* query = (const float*)d_in[1];   // [1,Q]
    const float* bnd   = (const float*)d_in[2];   // boundary [N,D]
    const float* deg   = (const float*)d_in[3];   // degree_out [N]
    const float* Wr    = (const float*)d_in[4];   // [2R*D, Q]
    const float* br    = (const float*)d_in[5];   // [2R*D]
    const float* Wlin  = (const float*)d_in[6];   // [D, 13D]
    const float* blin  = (const float*)d_in[7];   // [D]
    const int*   ei    = (const int*)d_in[8];     // edge_index [2,E] int32
    const int*   ea    = (const int*)d_in[9];     // edge_attr [E] int32
    float*       out   = (float*)d_out;           // [N,D]

    rel_kernel <<<(RELSZ * 32 + 255) / 256, 256>>>(Wr, br, query);
    scan_kernel<<<1, 1024>>>(deg);
    fill_kernel<<<(EE + 255) / 256, 256>>>(ei, ea);
    agg_kernel <<<(NN * 32 + 255) / 256, 256>>>(nf, bnd, deg);
    mean_kernel<<<1, 1024>>>();
    gemm_kernel<<<(NN + 127) / 128, 256>>>(nf, Wlin, blin, out);
}

// round 5
// speedup vs baseline: 1.8174x; 1.8174x over previous
#include <cuda_runtime.h>
#include <math.h>
#include <stdint.h>

#define NN    50000
#define EE    600000
#define DD    128
#define RREL2 474          /* 2R */
#define QQ    128
#define KTOT  1664         /* 13*D */
#define RELSZ (RREL2*DD)   /* 60672 */
#define NKT   52           /* K tiles of 32 */

// -------- scratch (static device globals; no allocation allowed) --------
__device__ __align__(16) float    g_rel[RELSZ];
__device__ int      g_row_start[NN + 1];
__device__ int      g_cursor[NN];
__device__ unsigned g_packed[EE];                 // src (16b) | attr<<16
__device__ __align__(16) float    g_feat4[(size_t)NN * 4 * DD]; // F [N,512]
__device__ float    g_logdeg[NN];
__device__ float    g_logdeg_mean;
// Wlin permuted to grouped-K, tile-major [kt][k][j], fp32:
__device__ __align__(16) float    g_wB[NKT * 4096];
__device__ float    g_probe[148 * 8];

// ========================= helpers ==========================
__device__ __forceinline__ void fma2(unsigned long long& d,
                                     unsigned long long a, unsigned long long b) {
    asm("fma.rn.f32x2 %0, %1, %2, %0;" : "+l"(d) : "l"(a), "l"(b));
}
__device__ __forceinline__ unsigned long long splat2(float x) {
    unsigned long long r;
    asm("mov.b64 %0, {%1, %1};" : "=l"(r) : "f"(x));
    return r;
}
__device__ __forceinline__ float2 unpack2(unsigned long long v) {
    float2 r;
    asm("mov.b64 {%0, %1}, %2;" : "=f"(r.x), "=f"(r.y) : "l"(v));
    return r;
}
__device__ __forceinline__ uint32_t smem_u32(const void* p) {
    uint32_t a;
    asm("{ .reg .u64 t; cvta.to.shared.u64 t, %1; cvt.u32.u64 %0, t; }"
        : "=r"(a) : "l"(p));
    return a;
}
__device__ __forceinline__ void cp16(uint32_t s, const void* g) {
    asm volatile("cp.async.cg.shared.global [%0], [%1], 16;" :: "r"(s), "l"(g));
}
#define CP_COMMIT() asm volatile("cp.async.commit_group;" ::: "memory")
#define CP_WAIT0()  asm volatile("cp.async.wait_group 0;" ::: "memory")

// ======================= K1: rel = query @ Wr^T + br =======================
__global__ void rel_kernel(const float* __restrict__ Wr,
                           const float* __restrict__ br,
                           const float* __restrict__ query) {
    int warp = (blockIdx.x * blockDim.x + threadIdx.x) >> 5;
    int lane = threadIdx.x & 31;
    if (warp >= RELSZ) return;
    const float* w = Wr + (size_t)warp * QQ;
    float s = w[lane]      * __ldg(&query[lane])
            + w[lane + 32] * __ldg(&query[lane + 32])
            + w[lane + 64] * __ldg(&query[lane + 64])
            + w[lane + 96] * __ldg(&query[lane + 96]);
    #pragma unroll
    for (int o = 16; o; o >>= 1) s += __shfl_xor_sync(0xffffffffu, s, o);
    if (lane == 0) g_rel[warp] = s + br[warp];
}

// ============ K2: exclusive scan of (int)degree -> row_start, cursor =========
__global__ void scan_kernel(const float* __restrict__ degout) {
    __shared__ int wsum[32];
    __shared__ int carry;
    int t = threadIdx.x, lane = t & 31, w = t >> 5;
    if (t == 0) carry = 0;
    __syncthreads();
    for (int base = 0; base < NN; base += 1024) {
        int i = base + t;
        int v = (i < NN) ? (int)(degout[i] + 0.5f) : 0;
        int x = v;
        #pragma unroll
        for (int o = 1; o < 32; o <<= 1) {
            int y = __shfl_up_sync(0xffffffffu, x, o);
            if (lane >= o) x += y;
        }
        if (lane == 31) wsum[w] = x;
        __syncthreads();
        if (w == 0) {
            int s = wsum[lane];
            #pragma unroll
            for (int o = 1; o < 32; o <<= 1) {
                int y = __shfl_up_sync(0xffffffffu, s, o);
                if (lane >= o) s += y;
            }
            wsum[lane] = s;
        }
        __syncthreads();
        int excl = x - v + (w ? wsum[w - 1] : 0) + carry;
        if (i < NN) { g_row_start[i] = excl; g_cursor[i] = excl; }
        __syncthreads();
        if (t == 1023) carry = excl + v;
        __syncthreads();
    }
    if (t == 0) g_row_start[NN] = carry;
}

// ================= K3: bucket edges into CSR slots ========================
__global__ void fill_kernel(const int* __restrict__ ei,
                            const int* __restrict__ ea) {
    int e = blockIdx.x * blockDim.x + threadIdx.x;
    if (e >= EE) return;
    int src = ei[e];
    int dst = ei[EE + e];
    int a   = ea[e];
    int pos = atomicAdd(&g_cursor[dst], 1);
    g_packed[pos] = (unsigned)src | ((unsigned)a << 16);
}

// ====== K4: per-node gather reduction, float4 per lane (cols 4l..4l+3) ======
__global__ void agg_kernel(const float* __restrict__ nf,
                           const float* __restrict__ boundary,
                           const float* __restrict__ degout) {
    int n    = (blockIdx.x * blockDim.x + threadIdx.x) >> 5;
    int lane = threadIdx.x & 31;
    if (n >= NN) return;
    int beg = g_row_start[n], end = g_row_start[n + 1];
    int c0 = lane * 4;

    float4 sum = make_float4(0.f, 0.f, 0.f, 0.f);
    float4 sq  = make_float4(0.f, 0.f, 0.f, 0.f);
    float4 mx  = make_float4(-INFINITY, -INFINITY, -INFINITY, -INFINITY);
    float4 mn  = make_float4(INFINITY, INFINITY, INFINITY, INFINITY);

    for (int e = beg; e < end; e++) {
        unsigned p = g_packed[e];
        float4 s4 = *(const float4*)(nf    + (size_t)(p & 0xFFFFu) * DD + c0);
        float4 f4 = *(const float4*)(g_rel + (size_t)(p >> 16) * DD + c0);
        float m0 = s4.x * f4.x, m1 = s4.y * f4.y, m2 = s4.z * f4.z, m3 = s4.w * f4.w;
        sum.x += m0; sum.y += m1; sum.z += m2; sum.w += m3;
        sq.x += m0 * m0; sq.y += m1 * m1; sq.z += m2 * m2; sq.w += m3 * m3;
        mx.x = fmaxf(mx.x, m0); mx.y = fmaxf(mx.y, m1);
        mx.z = fmaxf(mx.z, m2); mx.w = fmaxf(mx.w, m3);
        mn.x = fminf(mn.x, m0); mn.y = fminf(mn.y, m1);
        mn.z = fminf(mn.z, m2); mn.w = fminf(mn.w, m3);
    }

    float d0  = degout[n];
    float deg = d0 + 1.0f;
    bool  has_edge = (d0 > 0.0f);
    float inv = 1.0f / deg;
    float4 b = *(const float4*)(boundary + (size_t)n * DD + c0);

    float sums[4] = {sum.x, sum.y, sum.z, sum.w};
    float sqs[4]  = {sq.x, sq.y, sq.z, sq.w};
    float mxs[4]  = {mx.x, mx.y, mx.z, mx.w};
    float mns[4]  = {mn.x, mn.y, mn.z, mn.w};
    float bs[4]   = {b.x, b.y, b.z, b.w};

    #pragma unroll
    for (int u = 0; u < 4; u++) {
        float bb = bs[u];
        float mean   = (sums[u] + bb) * inv;
        float sqmean = (sqs[u] + bb * bb) * inv;
        float vmx = has_edge ? mxs[u] : 0.0f;
        float vmn = has_edge ? mns[u] : 0.0f;
        vmx = fmaxf(vmx, bb);
        vmn = fminf(vmn, bb);
        float sd = sqrtf(fmaxf(sqmean - mean * mean, 1e-6f));
        float4 v = make_float4(mean, vmx, vmn, sd);
        *(float4*)&g_feat4[(size_t)n * 512 + (c0 + u) * 4] = v;
    }
    if (lane == 0) g_logdeg[n] = logf(deg);
}

// ================= K5: deterministic mean of log(deg) ======================
__global__ void mean_kernel() {
    __shared__ float sh[1024];
    float s = 0.f;
    for (int i = threadIdx.x; i < NN; i += 1024) s += g_logdeg[i];
    sh[threadIdx.x] = s;
    __syncthreads();
    for (int o = 512; o; o >>= 1) {
        if (threadIdx.x < (unsigned)o) sh[threadIdx.x] += sh[threadIdx.x + o];
        __syncthreads();
    }
    if (threadIdx.x == 0) g_logdeg_mean = sh[0] / (float)NN;
}

// ===== K5b: permute Wlin to grouped-K tile-major [kt][k][j], fp32 =====
// grouped col cp: cp<128 -> c=cp ; else m=cp-128, s=m>>9, fidx=m&511, c=128+3*fidx+s
__global__ void wperm_kernel(const float* __restrict__ Wlin) {
    __shared__ float tmp[32 * 129];
    int kt = blockIdx.x;
    int t  = threadIdx.x;
    #pragma unroll
    for (int i = 0; i < 16; i++) {
        int e  = t + i * 256;          // 0..4095
        int j  = e >> 5;
        int kl = e & 31;
        int cp = kt * 32 + kl;
        int c;
        if (cp < 128) c = cp;
        else { int m = cp - 128; int s = m >> 9; int f = m & 511; c = 128 + 3 * f + s; }
        tmp[kl * 129 + j] = Wlin[(size_t)j * KTOT + c];
    }
    __syncthreads();
    #pragma unroll
    for (int i = 0; i < 16; i++) {
        int e = t + i * 256;
        g_wB[(size_t)kt * 4096 + e] = tmp[(e >> 7) * 129 + (e & 127)];
    }
}

// ================== K6: SIMT f32x2 GEMM, fused epilogue =====================
// 128x128 tile, BK=32, 256 threads, 8x8 per thread (j-packed f32x2 accs).
#define ASTR 36
#define SM_BS0 0
#define SM_AS  8192              /* floats: Bs = 2*4096 */
#define SM_SC  (8192 + 128 * ASTR)
#define SMEM_F (SM_SC + 256)
#define SMEM_BYTES (SMEM_F * 4)

__global__ void __launch_bounds__(256)
gemm_simt(const float* __restrict__ nf,
          const float* __restrict__ blin,
          float* __restrict__ out) {
    extern __shared__ float sm[];
    float* Bs  = sm;                 // [2][32*128]
    float* As  = sm + SM_AS;         // [128][ASTR]
    float* sc1 = sm + SM_SC;
    float* sc2 = sc1 + 128;

    const int t  = threadIdx.x;
    const int n0 = blockIdx.x * 128;
    const int tx = t & 15;
    const int ty = t >> 4;
    const int cq = t & 7;            // c-quad for A build
    const int nl = t >> 3;           // base n_local for A build (stride 32 over i)

    if (t < 128) {
        int n = n0 + t;
        float scale = 0.f;
        if (n < NN) scale = g_logdeg[n] / (g_logdeg_mean + 1e-10f);
        sc1[t] = scale;
        sc2[t] = 1.0f / fmaxf(scale, 0.01f);
    }
    __syncthreads();

    const uint32_t bsAddr = smem_u32(Bs);

    // ---- A tile prefetch into registers (grouped-K virtual X) ----
    float4 av[4];
    auto ldA = [&](int kt) {
        int grp = (kt >= 36) ? 3 : (kt >= 20) ? 2 : (kt >= 4) ? 1 : 0;
        #pragma unroll
        for (int i = 0; i < 4; i++) {
            int nli = nl + i * 32;
            int n = n0 + nli;
            float4 v = make_float4(0.f, 0.f, 0.f, 0.f);
            if (n < NN) {
                if (grp == 0) {
                    v = *(const float4*)&nf[(size_t)n * DD + kt * 32 + cq * 4];
                } else {
                    int f0 = kt * 32 - ((grp == 3) ? 1152 : (grp == 2) ? 640 : 128);
                    v = *(const float4*)&g_feat4[(size_t)n * 512 + f0 + cq * 4];
                    if (grp >= 2) {
                        float s = (grp == 3) ? sc2[nli] : sc1[nli];
                        v.x *= s; v.y *= s; v.z *= s; v.w *= s;
                    }
                }
            }
            av[i] = v;
        }
    };
    auto stA = [&]() {
        #pragma unroll
        for (int i = 0; i < 4; i++)
            *(float4*)&As[(nl + i * 32) * ASTR + cq * 4] = av[i];
    };
    auto ldB = [&](int kt, int buf) {
        const float* src = &g_wB[(size_t)kt * 4096];
        uint32_t dst = bsAddr + buf * 16384 + t * 16;
        #pragma unroll
        for (int i = 0; i < 4; i++)
            cp16(dst + i * 4096, src + t * 4 + i * 1024);
        CP_COMMIT();
    };

    unsigned long long acc[8][4];
    #pragma unroll
    for (int r = 0; r < 8; r++)
        #pragma unroll
        for (int p = 0; p < 4; p++) acc[r][p] = 0ull;

    ldA(0);
    ldB(0, 0);
    stA();
    CP_WAIT0();
    __syncthreads();

    int cur = 0;
    for (int kt = 0; kt < NKT; kt++) {
        if (kt + 1 < NKT) {
            ldA(kt + 1);
            ldB(kt + 1, cur ^ 1);
        }
        const float* Bc = &Bs[cur * 4096];
        #pragma unroll 4
        for (int kl = 0; kl < 32; kl++) {
            unsigned long long a2[8];
            #pragma unroll
            for (int r = 0; r < 4; r++) {
                a2[r]     = splat2(As[(ty * 4 + r) * ASTR + kl]);
                a2[r + 4] = splat2(As[(ty * 4 + 64 + r) * ASTR + kl]);
            }
            ulonglong2 b01 = *(const ulonglong2*)&Bc[kl * 128 + tx * 4];
            ulonglong2 b23 = *(const ulonglong2*)&Bc[kl * 128 + tx * 4 + 64];
            #pragma unroll
            for (int r = 0; r < 8; r++) {
                fma2(acc[r][0], a2[r], b01.x);
                fma2(acc[r][1], a2[r], b01.y);
                fma2(acc[r][2], a2[r], b23.x);
                fma2(acc[r][3], a2[r], b23.y);
            }
        }
        __syncthreads();           // everyone done reading As/Bs[cur]
        if (kt + 1 < NKT) {
            stA();
            CP_WAIT0();
        }
        __syncthreads();
        cur ^= 1;
    }

    // ---- epilogue: bias + relu ----
    float4 bl0 = __ldg((const float4*)&blin[tx * 4]);
    float4 bl1 = __ldg((const float4*)&blin[tx * 4 + 64]);
    #pragma unroll
    for (int r = 0; r < 8; r++) {
        int n = n0 + ty * 4 + ((r < 4) ? r : (64 + r - 4));
        if (n >= NN) continue;
        float2 p0 = unpack2(acc[r][0]);
        float2 p1 = unpack2(acc[r][1]);
        float2 p2 = unpack2(acc[r][2]);
        float2 p3 = unpack2(acc[r][3]);
        float4 o0, o1;
        o0.x = fmaxf(p0.x + bl0.x, 0.f);
        o0.y = fmaxf(p0.y + bl0.y, 0.f);
        o0.z = fmaxf(p1.x + bl0.z, 0.f);
        o0.w = fmaxf(p1.y + bl0.w, 0.f);
        o1.x = fmaxf(p2.x + bl1.x, 0.f);
        o1.y = fmaxf(p2.y + bl1.y, 0.f);
        o1.z = fmaxf(p3.x + bl1.z, 0.f);
        o1.w = fmaxf(p3.y + bl1.w, 0.f);
        *(float4*)&out[(size_t)n * DD + tx * 4]      = o0;
        *(float4*)&out[(size_t)n * DD + tx * 4 + 64] = o1;
    }
}

// ============ probe: is bf16 mma.sync native or emulated on this target? ====
// 1024 m16n8k16 bf16 MMAs on zeros per warp; duration visible in ncu top-3.
__global__ void probe_bf16() {
    float d[4][4];
    #pragma unroll
    for (int c = 0; c < 4; c++)
        #pragma unroll
        for (int i = 0; i < 4; i++) d[c][i] = 0.f;
    unsigned z = 0;
    for (int it = 0; it < 256; it++) {
        #pragma unroll
        for (int c = 0; c < 4; c++) {
            asm volatile(
                "mma.sync.aligned.m16n8k16.row.col.f32.bf16.bf16.f32 "
                "{%0,%1,%2,%3},{%4,%5,%6,%7},{%8,%9},{%0,%1,%2,%3};"
                : "+f"(d[c][0]), "+f"(d[c][1]), "+f"(d[c][2]), "+f"(d[c][3])
                : "r"(z), "r"(z), "r"(z), "r"(z), "r"(z), "r"(z));
        }
    }
    if ((threadIdx.x & 31) == 0) {
        float s = d[0][0] + d[1][1] + d[2][2] + d[3][3];
        g_probe[blockIdx.x * 8 + (threadIdx.x >> 5)] = s;
    }
}

// ============================== launch ====================================
extern "C" void kernel_launch(void* const* d_in, const int* in_sizes, int n_in,
                              void* d_out, int out_size) {
    const float* nf    = (const float*)d_in[0];   // node_features [N,D]
    const float* query = (const float*)d_in[1];   // [1,Q]
    const float* bnd   = (const float*)d_in[2];   // boundary [N,D]
    const float* deg   = (const float*)d_in[3];   // degree_out [N]
    const float* Wr    = (const float*)d_in[4];   // [2R*D, Q]
    const float* br    = (const float*)d_in[5];   // [2R*D]
    const float* Wlin  = (const float*)d_in[6];   // [D, 13D]
    const float* blin  = (const float*)d_in[7];   // [D]
    const int*   ei    = (const int*)d_in[8];     // edge_index [2,E] int32
    const int*   ea    = (const int*)d_in[9];     // edge_attr [E] int32
    float*       out   = (float*)d_out;           // [N,D]

    cudaFuncSetAttribute(gemm_simt, cudaFuncAttributeMaxDynamicSharedMemorySize,
                         SMEM_BYTES);

    rel_kernel  <<<(RELSZ * 32 + 255) / 256, 256>>>(Wr, br, query);
    scan_kernel <<<1, 1024>>>(deg);
    fill_kernel <<<(EE + 255) / 256, 256>>>(ei, ea);
    wperm_kernel<<<NKT, 256>>>(Wlin);
    agg_kernel  <<<(NN * 32 + 255) / 256, 256>>>(nf, bnd, deg);
    mean_kernel <<<1, 1024>>>();
    gemm_simt   <<<(NN + 127) / 128, 256, SMEM_BYTES>>>(nf, blin, out);
    probe_bf16  <<<148, 256>>>();
}